// round 13
// baseline (speedup 1.0000x reference)
#include <cuda_runtime.h>
#include <cuda_bf16.h>

// x is [B=4096, T=512, D=4] batch_first; H=32
#define DIN      4
#define EPW      8          // batch elements per warp-PAIR
#define NPAIR    4          // warp pairs per block
#define NTHREADS 256        // 8 warps
#define ELB      (NPAIR * EPW)   // 32 elements per block
#define CHUNK    16
#define WPAD     36         // padded weight row stride (floats)

typedef unsigned long long u64;

static __device__ __forceinline__ u64 pk2(float lo, float hi) {
    u64 r; asm("mov.b64 %0,{%1,%2};" : "=l"(r) : "f"(lo), "f"(hi)); return r;
}
static __device__ __forceinline__ void upk2(u64 v, float& lo, float& hi) {
    asm("mov.b64 {%0,%1},%2;" : "=f"(lo), "=f"(hi) : "l"(v));
}
static __device__ __forceinline__ u64 fma2(u64 a, u64 b, u64 c) {
    u64 d; asm("fma.rn.f32x2 %0,%1,%2,%3;" : "=l"(d) : "l"(a), "l"(b), "l"(c)); return d;
}
static __device__ __forceinline__ float sigf(float x) {
    return __fdividef(1.0f, 1.0f + __expf(-x));
}
static __device__ __forceinline__ float tanhfast(float x) {
    return __fdividef(2.0f, 1.0f + __expf(-2.0f * x)) - 1.0f;
}

// smem (floats): whh1 (128 x WPAD) | h1 | h2 | xbuf | gate-exchange
#define SM_FLOATS (128 * WPAD + 2 * NPAIR * EPW * 32 \
                   + NPAIR * EPW * CHUNK * 4 + NPAIR * EPW * 32 * 2)
#define SM_BYTES  (SM_FLOATS * 4)

__global__ __launch_bounds__(NTHREADS, 1)
void lstm2_kernel(const float* __restrict__ x,
                  const float* __restrict__ Wih0, const float* __restrict__ Whh0,
                  const float* __restrict__ bih0, const float* __restrict__ bhh0,
                  const float* __restrict__ Wih1, const float* __restrict__ Whh1,
                  const float* __restrict__ bih1, const float* __restrict__ bhh1,
                  const float* __restrict__ Wout, const float* __restrict__ bout,
                  float* __restrict__ out, int T)
{
    extern __shared__ float sm[];
    float* s_whh1 = sm;                           // [128][WPAD]
    float* s_h1   = s_whh1 + 128 * WPAD;          // [NPAIR][EPW][32]
    float* s_h2   = s_h1 + NPAIR * EPW * 32;
    float* s_x    = s_h2 + NPAIR * EPW * 32;      // [NPAIR][EPW][CHUNK][4]
    float* s_gx   = s_x + NPAIR * EPW * CHUNK * 4;// [NPAIR][EPW][32][2] {tanh_g, sig_o}

    const int tid  = threadIdx.x;
    const int w    = tid >> 5;
    const int j    = tid & 31;            // hidden unit owned by this lane
    const int pair = w >> 1;
    const int role = w & 1;               // 0: rows i,f (owns c/h)   1: rows g,o
    const int eb   = (blockIdx.x * NPAIR + pair) * EPW;
    const int T4   = T * DIN;

    // ---- stage ONLY whh1 into padded smem rows (once) ----
    for (int i = tid; i < 4096; i += NTHREADS) {
        int r = i >> 5, k = i & 31;
        s_whh1[r * WPAD + k] = Whh1[i];
    }

    float* h1w = s_h1 + pair * (EPW * 32);
    float* h2w = s_h2 + pair * (EPW * 32);
    float* xw  = s_x  + pair * (EPW * CHUNK * 4);
    float* gxw = s_gx + pair * (EPW * 64);

    if (role == 0) {
#pragma unroll
        for (int e = 0; e < EPW; ++e) { h1w[e * 32 + j] = 0.f; h2w[e * 32 + j] = 0.f; }
    }

    // this warp's two gate rows: role0 -> {i,f} = {j, 32+j}; role1 -> {g,o} = {64+j, 96+j}
    const int rA = role * 64 + j;
    const int rB = role * 64 + 32 + j;

    // ---- register-stationary weights (adjacent fp32 pair == f32x2 layout) ----
    u64 wh0A[16], wh0B[16], wi1A[16], wi1B[16];
#pragma unroll
    for (int m = 0; m < 16; ++m) {
        wh0A[m] = *(const u64*)(Whh0 + rA * 32 + 2 * m);
        wh0B[m] = *(const u64*)(Whh0 + rB * 32 + 2 * m);
        wi1A[m] = *(const u64*)(Wih1 + rA * 32 + 2 * m);
        wi1B[m] = *(const u64*)(Wih1 + rB * 32 + 2 * m);
    }
    u64 wiA[2], wiB[2], b0A, b0B, b1A, b1B;
    {
        float4 wa = *(const float4*)(Wih0 + rA * 4);
        float4 wb = *(const float4*)(Wih0 + rB * 4);
        wiA[0] = pk2(wa.x, wa.y); wiA[1] = pk2(wa.z, wa.w);
        wiB[0] = pk2(wb.x, wb.y); wiB[1] = pk2(wb.z, wb.w);
        b0A = pk2(bih0[rA] + bhh0[rA], 0.f);
        b0B = pk2(bih0[rB] + bhh0[rB], 0.f);
        b1A = pk2(bih1[rA] + bhh1[rA], 0.f);
        b1B = pk2(bih1[rB] + bhh1[rB], 0.f);
    }
    const float wj = Wout[j];
    const float bo = bout[0];

    float c1[EPW], c2[EPW];
#pragma unroll
    for (int e = 0; e < EPW; ++e) { c1[e] = 0.f; c2[e] = 0.f; }

#define PAIRBAR() asm volatile("bar.sync %0, 64;" :: "r"(pair + 1) : "memory")

    __syncthreads();

    for (int t = 0; t < T; ++t) {
        // ---- stage x chunk (role 0 loads; pair barrier publishes) ----
        if ((t & (CHUNK - 1)) == 0) {
            if (role == 0) {
#pragma unroll
                for (int n = 0; n < (EPW * CHUNK) / 32; ++n) {  // 4 float4 per lane
                    int i  = n * 32 + j;           // float4 index: [el][tt]
                    int el = i >> 4;
                    int r  = i & (CHUNK - 1);
                    int tg = t + r;
                    float4 v = (tg < T)
                        ? *(const float4*)(x + (size_t)(eb + el) * T4 + tg * DIN)
                        : make_float4(0.f, 0.f, 0.f, 0.f);
                    *(float4*)(xw + i * 4) = v;
                }
            }
            PAIRBAR();
        }
        const int ts = t & (CHUNK - 1);

        // ================= layer 0 : this warp's 2 gate rows =================
        u64 accA[EPW], accB[EPW];
#pragma unroll
        for (int e = 0; e < EPW; ++e) {
            ulonglong2 xx = *(const ulonglong2*)(xw + e * (CHUNK * 4) + ts * 4);
            accA[e] = fma2(wiA[1], xx.y, fma2(wiA[0], xx.x, b0A));
            accB[e] = fma2(wiB[1], xx.y, fma2(wiB[0], xx.x, b0B));
        }
#pragma unroll
        for (int kk = 0; kk < 8; ++kk) {
            const u64 wA0 = wh0A[2 * kk], wA1 = wh0A[2 * kk + 1];
            const u64 wB0 = wh0B[2 * kk], wB1 = wh0B[2 * kk + 1];
#pragma unroll
            for (int e = 0; e < EPW; ++e) {
                ulonglong2 hh = *(const ulonglong2*)(h1w + e * 32 + kk * 4); // broadcast
                accA[e] = fma2(wA0, hh.x, accA[e]);
                accA[e] = fma2(wA1, hh.y, accA[e]);
                accB[e] = fma2(wB0, hh.x, accB[e]);
                accB[e] = fma2(wB1, hh.y, accB[e]);
            }
        }
        if (role == 1) {   // g,o: activate and publish
#pragma unroll
            for (int e = 0; e < EPW; ++e) {
                float lo, hi;
                upk2(accA[e], lo, hi); float g_ = lo + hi;
                upk2(accB[e], lo, hi); float o_ = lo + hi;
                *(float2*)(gxw + (e * 32 + j) * 2) =
                    make_float2(tanhfast(g_), sigf(o_));
            }
        }
        PAIRBAR();   // gates ready; also: all h1_old reads done
        if (role == 0) {   // i,f: update c, write h1
#pragma unroll
            for (int e = 0; e < EPW; ++e) {
                float lo, hi;
                upk2(accA[e], lo, hi); float i_ = lo + hi;
                upk2(accB[e], lo, hi); float f_ = lo + hi;
                float2 q = *(const float2*)(gxw + (e * 32 + j) * 2);
                float c = fmaf(sigf(f_), c1[e], sigf(i_) * q.x);
                c1[e] = c;
                h1w[e * 32 + j] = q.y * tanhfast(c);
            }
        }
        PAIRBAR();   // h1_new visible to both warps

        // ================= layer 1 =================
#pragma unroll
        for (int e = 0; e < EPW; ++e) { accA[e] = b1A; accB[e] = b1B; }
#pragma unroll
        for (int kk = 0; kk < 8; ++kk) {
            const u64 wA0 = wi1A[2 * kk], wA1 = wi1A[2 * kk + 1];
            const u64 wB0 = wi1B[2 * kk], wB1 = wi1B[2 * kk + 1];
            ulonglong2 whAx = *(const ulonglong2*)(s_whh1 + rA * WPAD + kk * 4);
            ulonglong2 whBx = *(const ulonglong2*)(s_whh1 + rB * WPAD + kk * 4);
#pragma unroll
            for (int e = 0; e < EPW; ++e) {
                ulonglong2 ha = *(const ulonglong2*)(h1w + e * 32 + kk * 4); // broadcast
                ulonglong2 hb = *(const ulonglong2*)(h2w + e * 32 + kk * 4); // broadcast
                accA[e] = fma2(wA0, ha.x, accA[e]);
                accA[e] = fma2(wA1, ha.y, accA[e]);
                accA[e] = fma2(whAx.x, hb.x, accA[e]);
                accA[e] = fma2(whAx.y, hb.y, accA[e]);
                accB[e] = fma2(wB0, ha.x, accB[e]);
                accB[e] = fma2(wB1, ha.y, accB[e]);
                accB[e] = fma2(whBx.x, hb.x, accB[e]);
                accB[e] = fma2(whBx.y, hb.y, accB[e]);
            }
        }
        if (role == 1) {
#pragma unroll
            for (int e = 0; e < EPW; ++e) {
                float lo, hi;
                upk2(accA[e], lo, hi); float g_ = lo + hi;
                upk2(accB[e], lo, hi); float o_ = lo + hi;
                *(float2*)(gxw + (e * 32 + j) * 2) =
                    make_float2(tanhfast(g_), sigf(o_));
            }
        }
        PAIRBAR();   // gates ready; all h2_old reads done
        if (role == 0) {
#pragma unroll
            for (int e = 0; e < EPW; ++e) {
                float lo, hi;
                upk2(accA[e], lo, hi); float i_ = lo + hi;
                upk2(accB[e], lo, hi); float f_ = lo + hi;
                float2 q = *(const float2*)(gxw + (e * 32 + j) * 2);
                float c = fmaf(sigf(f_), c2[e], sigf(i_) * q.x);
                c2[e] = c;
                h2w[e * 32 + j] = q.y * tanhfast(c);
            }
        }
        PAIRBAR();   // h2_new committed before next step reads it
    }

    // ---- final projection out[b] = h2 . Wout + bout (role-0 warps) ----
    if (role == 0) {
#pragma unroll
        for (int e = 0; e < EPW; ++e) {
            float v = h2w[e * 32 + j] * wj;
#pragma unroll
            for (int off = 16; off; off >>= 1)
                v += __shfl_xor_sync(0xffffffffu, v, off);
            if (j == 0) out[eb + e] = v + bo;
        }
    }
#undef PAIRBAR
}

extern "C" void kernel_launch(void* const* d_in, const int* in_sizes, int n_in,
                              void* d_out, int out_size)
{
    const float* x    = (const float*)d_in[0];
    const float* Wih0 = (const float*)d_in[1];
    const float* Whh0 = (const float*)d_in[2];
    const float* bih0 = (const float*)d_in[3];
    const float* bhh0 = (const float*)d_in[4];
    const float* Wih1 = (const float*)d_in[5];
    const float* Whh1 = (const float*)d_in[6];
    const float* bih1 = (const float*)d_in[7];
    const float* bhh1 = (const float*)d_in[8];
    const float* Wout = (const float*)d_in[9];
    const float* bout = (const float*)d_in[10];
    float* out = (float*)d_out;

    const int B = out_size;                 // 4096
    const int T = in_sizes[0] / (B * DIN);  // 512

    cudaFuncSetAttribute(lstm2_kernel,
                         cudaFuncAttributeMaxDynamicSharedMemorySize, SM_BYTES);
    lstm2_kernel<<<B / ELB, NTHREADS, SM_BYTES>>>(
        x, Wih0, Whh0, bih0, bhh0, Wih1, Whh1, bih1, bhh1, Wout, bout, out, T);
}

// round 17
// speedup vs baseline: 1.2307x; 1.2307x over previous
#include <cuda_runtime.h>
#include <cuda_bf16.h>

// x is [B=4096, T=512, D=4] batch_first; H=32
#define DIN      4
#define EPW      4          // batch elements per warp-PAIR
#define EHALF    (EPW / 2)
#define NPAIR    8          // warp pairs per block
#define NTHREADS 512        // 16 warps
#define ELB      (NPAIR * EPW)   // 32 elements per block
#define CHUNK    16
#define WPAD     36         // padded weight row stride (floats)

typedef unsigned long long u64;

static __device__ __forceinline__ u64 pk2(float lo, float hi) {
    u64 r; asm("mov.b64 %0,{%1,%2};" : "=l"(r) : "f"(lo), "f"(hi)); return r;
}
static __device__ __forceinline__ void upk2(u64 v, float& lo, float& hi) {
    asm("mov.b64 {%0,%1},%2;" : "=f"(lo), "=f"(hi) : "l"(v));
}
static __device__ __forceinline__ u64 fma2(u64 a, u64 b, u64 c) {
    u64 d; asm("fma.rn.f32x2 %0,%1,%2,%3;" : "=l"(d) : "l"(a), "l"(b), "l"(c)); return d;
}
static __device__ __forceinline__ float sigf(float x) {
    return __fdividef(1.0f, 1.0f + __expf(-x));
}
static __device__ __forceinline__ float tanhfast(float x) {
    return __fdividef(2.0f, 1.0f + __expf(-2.0f * x)) - 1.0f;
}

// smem (floats): whh0|wih1|whh1 (128xWPAD each) | h1 | h2 | xbuf | gx0 | gx1
#define SM_FLOATS (3 * 128 * WPAD + 2 * NPAIR * EPW * 32 \
                   + NPAIR * EPW * CHUNK * 4 + 2 * NPAIR * EPW * 32 * 2)
#define SM_BYTES  (SM_FLOATS * 4)

__global__ __launch_bounds__(NTHREADS, 1)
void lstm2_kernel(const float* __restrict__ x,
                  const float* __restrict__ Wih0, const float* __restrict__ Whh0,
                  const float* __restrict__ bih0, const float* __restrict__ bhh0,
                  const float* __restrict__ Wih1, const float* __restrict__ Whh1,
                  const float* __restrict__ bih1, const float* __restrict__ bhh1,
                  const float* __restrict__ Wout, const float* __restrict__ bout,
                  float* __restrict__ out, int T)
{
    extern __shared__ float sm[];
    float* s_whh0 = sm;                           // [128][WPAD]
    float* s_wih1 = s_whh0 + 128 * WPAD;
    float* s_whh1 = s_wih1 + 128 * WPAD;
    float* s_h1   = s_whh1 + 128 * WPAD;          // [NPAIR][EPW][32]
    float* s_h2   = s_h1 + NPAIR * EPW * 32;
    float* s_x    = s_h2 + NPAIR * EPW * 32;      // [NPAIR][EPW][CHUNK][4]
    float* s_gx0  = s_x + NPAIR * EPW * CHUNK * 4;// [NPAIR][EPW][32][2] layer0 exchange
    float* s_gx1  = s_gx0 + NPAIR * EPW * 64;     // layer1 exchange

    const int tid  = threadIdx.x;
    const int w    = tid >> 5;
    const int j    = tid & 31;            // hidden unit owned by this lane
    const int pair = w >> 1;
    const int role = w & 1;               // 0: rows i,f   1: rows g,o
    const int eb   = (blockIdx.x * NPAIR + pair) * EPW;
    const int T4   = T * DIN;

    // ---- stage recurrent/input weights into padded smem rows (once) ----
    for (int i = tid; i < 4096; i += NTHREADS) {
        int r = i >> 5, k = i & 31;
        s_whh0[r * WPAD + k] = Whh0[i];
        s_wih1[r * WPAD + k] = Wih1[i];
        s_whh1[r * WPAD + k] = Whh1[i];
    }

    float* h1w  = s_h1  + pair * (EPW * 32);
    float* h2w  = s_h2  + pair * (EPW * 32);
    float* xw   = s_x   + pair * (EPW * CHUNK * 4);
    float* gx0w = s_gx0 + pair * (EPW * 64);
    float* gx1w = s_gx1 + pair * (EPW * 64);

    if (role == 0) {
#pragma unroll
        for (int e = 0; e < EPW; ++e) { h1w[e * 32 + j] = 0.f; h2w[e * 32 + j] = 0.f; }
    }

    // this warp's two gate rows: role0 -> {i,f} = {j, 32+j}; role1 -> {g,o} = {64+j, 96+j}
    const int rA = role * 64 + j;
    const int rB = role * 64 + 32 + j;

    u64 wiA[2], wiB[2], b0A, b0B, b1A, b1B;
    {
        float4 wa = *(const float4*)(Wih0 + rA * 4);
        float4 wb = *(const float4*)(Wih0 + rB * 4);
        wiA[0] = pk2(wa.x, wa.y); wiA[1] = pk2(wa.z, wa.w);
        wiB[0] = pk2(wb.x, wb.y); wiB[1] = pk2(wb.z, wb.w);
        b0A = pk2(bih0[rA] + bhh0[rA], 0.f);
        b0B = pk2(bih0[rB] + bhh0[rB], 0.f);
        b1A = pk2(bih1[rA] + bhh1[rA], 0.f);
        b1B = pk2(bih1[rB] + bhh1[rB], 0.f);
    }
    const float wj = Wout[j];
    const float bo = bout[0];

    // each warp owns c for its half of the elements (role0: lo, role1: hi)
    float c1[EHALF], c2[EHALF];
#pragma unroll
    for (int e = 0; e < EHALF; ++e) { c1[e] = 0.f; c2[e] = 0.f; }

#define PAIRBAR() asm volatile("bar.sync %0, 64;" :: "r"(pair + 1) : "memory")

    __syncthreads();

    for (int t = 0; t < T; ++t) {
        // ---- stage x chunk (role 0 loads; pair barrier publishes) ----
        if ((t & (CHUNK - 1)) == 0) {
            if (role == 0) {
#pragma unroll
                for (int n = 0; n < (EPW * CHUNK) / 32; ++n) {  // 2 float4 per lane
                    int i  = n * 32 + j;           // float4 index: [el][tt]
                    int el = i >> 4;
                    int r  = i & (CHUNK - 1);
                    int tg = t + r;
                    float4 v = (tg < T)
                        ? *(const float4*)(x + (size_t)(eb + el) * T4 + tg * DIN)
                        : make_float4(0.f, 0.f, 0.f, 0.f);
                    *(float4*)(xw + i * 4) = v;
                }
            }
            PAIRBAR();
        }
        const int ts = t & (CHUNK - 1);

        // ================= layer 0 : this warp's 2 gate rows =================
        u64 accA[EPW], accB[EPW];
#pragma unroll
        for (int e = 0; e < EPW; ++e) {
            ulonglong2 xx = *(const ulonglong2*)(xw + e * (CHUNK * 4) + ts * 4);
            accA[e] = fma2(wiA[1], xx.y, fma2(wiA[0], xx.x, b0A));
            accB[e] = fma2(wiB[1], xx.y, fma2(wiB[0], xx.x, b0B));
        }
#pragma unroll
        for (int kk = 0; kk < 8; ++kk) {
            ulonglong2 wdA = *(const ulonglong2*)(s_whh0 + rA * WPAD + kk * 4);
            ulonglong2 wdB = *(const ulonglong2*)(s_whh0 + rB * WPAD + kk * 4);
#pragma unroll
            for (int e = 0; e < EPW; ++e) {
                ulonglong2 hh = *(const ulonglong2*)(h1w + e * 32 + kk * 4); // broadcast
                accA[e] = fma2(wdA.x, hh.x, accA[e]);
                accA[e] = fma2(wdA.y, hh.y, accA[e]);
                accB[e] = fma2(wdB.x, hh.x, accB[e]);
                accB[e] = fma2(wdB.y, hh.y, accB[e]);
            }
        }
        // publish activated gates for the OTHER role's half
        if (role == 0) {
#pragma unroll
            for (int e = EHALF; e < EPW; ++e) {
                float lo, hi;
                upk2(accA[e], lo, hi); float i_ = lo + hi;
                upk2(accB[e], lo, hi); float f_ = lo + hi;
                *(float2*)(gx0w + (e * 32 + j) * 2) = make_float2(sigf(i_), sigf(f_));
            }
        } else {
#pragma unroll
            for (int e = 0; e < EHALF; ++e) {
                float lo, hi;
                upk2(accA[e], lo, hi); float g_ = lo + hi;
                upk2(accB[e], lo, hi); float o_ = lo + hi;
                *(float2*)(gx0w + (e * 32 + j) * 2) = make_float2(tanhfast(g_), sigf(o_));
            }
        }
        PAIRBAR();   // B1: gates published; all h1_old reads done
        // each role updates c/h for its OWN half (parallel epilogue)
        if (role == 0) {
#pragma unroll
            for (int e = 0; e < EHALF; ++e) {
                float lo, hi;
                upk2(accA[e], lo, hi); float i_ = lo + hi;
                upk2(accB[e], lo, hi); float f_ = lo + hi;
                float2 q = *(const float2*)(gx0w + (e * 32 + j) * 2); // (tanh_g, sig_o)
                float c = fmaf(sigf(f_), c1[e], sigf(i_) * q.x);
                c1[e] = c;
                h1w[e * 32 + j] = q.y * tanhfast(c);
            }
        } else {
#pragma unroll
            for (int e = EHALF; e < EPW; ++e) {
                float lo, hi;
                upk2(accA[e], lo, hi); float g_ = lo + hi;
                upk2(accB[e], lo, hi); float o_ = lo + hi;
                float2 q = *(const float2*)(gx0w + (e * 32 + j) * 2); // (sig_i, sig_f)
                float c = fmaf(q.y, c1[e - EHALF], q.x * tanhfast(g_));
                c1[e - EHALF] = c;
                h1w[e * 32 + j] = sigf(o_) * tanhfast(c);
            }
        }
        PAIRBAR();   // B2: h1_new visible to both warps

        // ================= layer 1 =================
#pragma unroll
        for (int e = 0; e < EPW; ++e) { accA[e] = b1A; accB[e] = b1B; }
#pragma unroll
        for (int kk = 0; kk < 8; ++kk) {
            ulonglong2 wiAx = *(const ulonglong2*)(s_wih1 + rA * WPAD + kk * 4);
            ulonglong2 wiBx = *(const ulonglong2*)(s_wih1 + rB * WPAD + kk * 4);
            ulonglong2 whAx = *(const ulonglong2*)(s_whh1 + rA * WPAD + kk * 4);
            ulonglong2 whBx = *(const ulonglong2*)(s_whh1 + rB * WPAD + kk * 4);
#pragma unroll
            for (int e = 0; e < EPW; ++e) {
                ulonglong2 ha = *(const ulonglong2*)(h1w + e * 32 + kk * 4); // broadcast
                ulonglong2 hb = *(const ulonglong2*)(h2w + e * 32 + kk * 4); // broadcast
                accA[e] = fma2(wiAx.x, ha.x, accA[e]);
                accA[e] = fma2(wiAx.y, ha.y, accA[e]);
                accA[e] = fma2(whAx.x, hb.x, accA[e]);
                accA[e] = fma2(whAx.y, hb.y, accA[e]);
                accB[e] = fma2(wiBx.x, ha.x, accB[e]);
                accB[e] = fma2(wiBx.y, ha.y, accB[e]);
                accB[e] = fma2(whBx.x, hb.x, accB[e]);
                accB[e] = fma2(whBx.y, hb.y, accB[e]);
            }
        }
        if (role == 0) {
#pragma unroll
            for (int e = EHALF; e < EPW; ++e) {
                float lo, hi;
                upk2(accA[e], lo, hi); float i_ = lo + hi;
                upk2(accB[e], lo, hi); float f_ = lo + hi;
                *(float2*)(gx1w + (e * 32 + j) * 2) = make_float2(sigf(i_), sigf(f_));
            }
        } else {
#pragma unroll
            for (int e = 0; e < EHALF; ++e) {
                float lo, hi;
                upk2(accA[e], lo, hi); float g_ = lo + hi;
                upk2(accB[e], lo, hi); float o_ = lo + hi;
                *(float2*)(gx1w + (e * 32 + j) * 2) = make_float2(tanhfast(g_), sigf(o_));
            }
        }
        PAIRBAR();   // B3: gates published; all h2_old reads done
        if (role == 0) {
#pragma unroll
            for (int e = 0; e < EHALF; ++e) {
                float lo, hi;
                upk2(accA[e], lo, hi); float i_ = lo + hi;
                upk2(accB[e], lo, hi); float f_ = lo + hi;
                float2 q = *(const float2*)(gx1w + (e * 32 + j) * 2);
                float c = fmaf(sigf(f_), c2[e], sigf(i_) * q.x);
                c2[e] = c;
                h2w[e * 32 + j] = q.y * tanhfast(c);
            }
        } else {
#pragma unroll
            for (int e = EHALF; e < EPW; ++e) {
                float lo, hi;
                upk2(accA[e], lo, hi); float g_ = lo + hi;
                upk2(accB[e], lo, hi); float o_ = lo + hi;
                float2 q = *(const float2*)(gx1w + (e * 32 + j) * 2);
                float c = fmaf(q.y, c2[e - EHALF], q.x * tanhfast(g_));
                c2[e - EHALF] = c;
                h2w[e * 32 + j] = sigf(o_) * tanhfast(c);
            }
        }
        // NO barrier here: h2 is next read only after B1+B2 of step t+1;
        // gate exchange is double-buffered (gx0/gx1), so no reuse race.
    }

    PAIRBAR();   // h2 halves complete before projection reads them

    // ---- final projection out[b] = h2 . Wout + bout (role-0 warps) ----
    if (role == 0) {
#pragma unroll
        for (int e = 0; e < EPW; ++e) {
            float v = h2w[e * 32 + j] * wj;
#pragma unroll
            for (int off = 16; off; off >>= 1)
                v += __shfl_xor_sync(0xffffffffu, v, off);
            if (j == 0) out[eb + e] = v + bo;
        }
    }
#undef PAIRBAR
}

extern "C" void kernel_launch(void* const* d_in, const int* in_sizes, int n_in,
                              void* d_out, int out_size)
{
    const float* x    = (const float*)d_in[0];
    const float* Wih0 = (const float*)d_in[1];
    const float* Whh0 = (const float*)d_in[2];
    const float* bih0 = (const float*)d_in[3];
    const float* bhh0 = (const float*)d_in[4];
    const float* Wih1 = (const float*)d_in[5];
    const float* Whh1 = (const float*)d_in[6];
    const float* bih1 = (const float*)d_in[7];
    const float* bhh1 = (const float*)d_in[8];
    const float* Wout = (const float*)d_in[9];
    const float* bout = (const float*)d_in[10];
    float* out = (float*)d_out;

    const int B = out_size;                 // 4096
    const int T = in_sizes[0] / (B * DIN);  // 512

    cudaFuncSetAttribute(lstm2_kernel,
                         cudaFuncAttributeMaxDynamicSharedMemorySize, SM_BYTES);
    lstm2_kernel<<<B / ELB, NTHREADS, SM_BYTES>>>(
        x, Wih0, Whh0, bih0, bhh0, Wih1, Whh1, bih1, bhh1, Wout, bout, out, T);
}